// round 14
// baseline (speedup 1.0000x reference)
#include <cuda_runtime.h>
#include <math.h>
#include <stdint.h>

#define EDIM 1024
#define NH   16
#define HD   64
#define BATCH 4
#define SEQ  1024
#define MTOT (BATCH*SEQ)      // 4096
#define NREL (2*SEQ - 1)      // 2047
#define NT   (SEQ/64)         // 16 k-tiles

// ---- scratch ----
__device__ float g_Q[MTOT*EDIM];
__device__ float g_K[MTOT*EDIM];
__device__ float g_V[MTOT*EDIM];
__device__ float g_ctx[MTOT*EDIM];
__device__ float g_Rk[NREL*HD];

__device__ __forceinline__ uint32_t f2tf32(float f) {
    uint32_t u;
    asm("cvt.rna.tf32.f32 %0, %1;" : "=r"(u) : "f"(f));
    return u;
}

#define MMA_TF32(acc, A0, A1, A2, A3, B0, B1)                                \
    asm volatile(                                                            \
        "mma.sync.aligned.m16n8k8.row.col.f32.tf32.tf32.f32 "               \
        "{%0,%1,%2,%3}, {%4,%5,%6,%7}, {%8,%9}, {%0,%1,%2,%3};"             \
        : "+f"((acc)[0]), "+f"((acc)[1]), "+f"((acc)[2]), "+f"((acc)[3])     \
        : "r"(A0), "r"(A1), "r"(A2), "r"(A3), "r"(B0), "r"(B1))

__device__ __forceinline__ void cpa16(uint32_t dst, const void* src) {
    asm volatile("cp.async.cg.shared.global [%0], [%1], 16;" :: "r"(dst), "l"(src));
}
__device__ __forceinline__ void cpa_commit() {
    asm volatile("cp.async.commit_group;");
}
__device__ __forceinline__ void cpa_wait_all() {
    asm volatile("cp.async.wait_group 0;" ::: "memory");
}

// ============================================================
// TF32 GEMM body (unchanged): C = A @ W^T + bias
// ============================================================
#define KC  32
#define PAD 36
#define GEMM_SMEM (2*2*128*PAD*4)   // 73728 bytes

__device__ __forceinline__ void gemm_body(
    const float* __restrict__ A, const float* __restrict__ W,
    const float* __restrict__ bias, float* __restrict__ C,
    int M, int N, int K, int round_out)
{
    extern __shared__ float smf[];
    uint32_t* As = (uint32_t*)smf;
    uint32_t* Bs = As + 2*128*PAD;

    const int tid  = threadIdx.x;
    const int lane = tid & 31;
    const int warp = tid >> 5;
    const int g    = lane >> 2;
    const int tig  = lane & 3;
    const int wm   = warp >> 2;
    const int wn   = warp & 3;
    const int bm   = blockIdx.y << 7;
    const int bn   = blockIdx.x << 7;

    const int r0 = tid >> 3;
    const int c4 = tid & 7;

    const float* Ap = A + (size_t)(bm + r0) * K + (c4 << 2);
    const float* Wp = W + (size_t)(bn + r0) * K + (c4 << 2);

    float acc[4][4][4];
#pragma unroll
    for (int mi = 0; mi < 4; mi++)
#pragma unroll
        for (int ni = 0; ni < 4; ni++)
#pragma unroll
            for (int q = 0; q < 4; q++) acc[mi][ni][q] = 0.f;

    float4 ra[4], rw[4];
    const int nt = K / KC;

#pragma unroll
    for (int i = 0; i < 4; i++) {
        ra[i] = *(const float4*)(Ap + (size_t)(i*32) * K);
        rw[i] = *(const float4*)(Wp + (size_t)(i*32) * K);
    }
    {
        uint32_t* dA = As;
        uint32_t* dB = Bs;
#pragma unroll
        for (int i = 0; i < 4; i++) {
            int off = (r0 + i*32)*PAD + (c4 << 2);
            dA[off+0] = f2tf32(ra[i].x); dA[off+1] = f2tf32(ra[i].y);
            dA[off+2] = f2tf32(ra[i].z); dA[off+3] = f2tf32(ra[i].w);
            dB[off+0] = f2tf32(rw[i].x); dB[off+1] = f2tf32(rw[i].y);
            dB[off+2] = f2tf32(rw[i].z); dB[off+3] = f2tf32(rw[i].w);
        }
    }

    for (int kt = 0; kt < nt; kt++) {
        __syncthreads();
        if (kt + 1 < nt) {
            const float* Ap2 = Ap + (size_t)(kt+1)*KC;
            const float* Wp2 = Wp + (size_t)(kt+1)*KC;
#pragma unroll
            for (int i = 0; i < 4; i++) {
                ra[i] = *(const float4*)(Ap2 + (size_t)(i*32) * K);
                rw[i] = *(const float4*)(Wp2 + (size_t)(i*32) * K);
            }
        }

        const uint32_t* cA = As + (kt & 1) * 128*PAD;
        const uint32_t* cB = Bs + (kt & 1) * 128*PAD;

#pragma unroll
        for (int kk = 0; kk < KC; kk += 8) {
            uint32_t af[4][4], bf[4][2];
#pragma unroll
            for (int mi = 0; mi < 4; mi++) {
                int r = (wm << 6) + (mi << 4);
                af[mi][0] = cA[(r + g    )*PAD + kk + tig    ];
                af[mi][1] = cA[(r + g + 8)*PAD + kk + tig    ];
                af[mi][2] = cA[(r + g    )*PAD + kk + tig + 4];
                af[mi][3] = cA[(r + g + 8)*PAD + kk + tig + 4];
            }
#pragma unroll
            for (int ni = 0; ni < 4; ni++) {
                int cn = (wn << 5) + (ni << 3);
                bf[ni][0] = cB[(cn + g)*PAD + kk + tig    ];
                bf[ni][1] = cB[(cn + g)*PAD + kk + tig + 4];
            }
#pragma unroll
            for (int mi = 0; mi < 4; mi++)
#pragma unroll
                for (int ni = 0; ni < 4; ni++)
                    MMA_TF32(acc[mi][ni], af[mi][0], af[mi][1], af[mi][2], af[mi][3],
                             bf[ni][0], bf[ni][1]);
        }

        if (kt + 1 < nt) {
            uint32_t* dA = As + ((kt+1) & 1) * 128*PAD;
            uint32_t* dB = Bs + ((kt+1) & 1) * 128*PAD;
#pragma unroll
            for (int i = 0; i < 4; i++) {
                int off = (r0 + i*32)*PAD + (c4 << 2);
                dA[off+0] = f2tf32(ra[i].x); dA[off+1] = f2tf32(ra[i].y);
                dA[off+2] = f2tf32(ra[i].z); dA[off+3] = f2tf32(ra[i].w);
                dB[off+0] = f2tf32(rw[i].x); dB[off+1] = f2tf32(rw[i].y);
                dB[off+2] = f2tf32(rw[i].z); dB[off+3] = f2tf32(rw[i].w);
            }
        }
    }

#pragma unroll
    for (int mi = 0; mi < 4; mi++) {
        int row = bm + (wm << 6) + (mi << 4) + g;
#pragma unroll
        for (int ni = 0; ni < 4; ni++) {
            int col = bn + (wn << 5) + (ni << 3) + (tig << 1);
            float b0 = bias[col], b1 = bias[col + 1];
            float v0 = acc[mi][ni][0] + b0, v1 = acc[mi][ni][1] + b1;
            float v2 = acc[mi][ni][2] + b0, v3 = acc[mi][ni][3] + b1;
            if (round_out) {
                v0 = __uint_as_float(f2tf32(v0));
                v1 = __uint_as_float(f2tf32(v1));
                v2 = __uint_as_float(f2tf32(v2));
                v3 = __uint_as_float(f2tf32(v3));
            }
            *(float2*)(C + (size_t)row       * N + col) = make_float2(v0, v1);
            *(float2*)(C + (size_t)(row + 8) * N + col) = make_float2(v2, v3);
        }
    }
}

__global__ __launch_bounds__(256) void gemm_qkv(
    const float* __restrict__ q, const float* __restrict__ k,
    const float* __restrict__ v,
    const float* __restrict__ Wq, const float* __restrict__ Wk,
    const float* __restrict__ Wv,
    const float* __restrict__ bq, const float* __restrict__ bk,
    const float* __restrict__ bv,
    float* __restrict__ Qg, float* __restrict__ Kg, float* __restrict__ Vg)
{
    const int z = blockIdx.z;
    const float* A = (z == 0) ? q  : (z == 1) ? k  : v;
    const float* W = (z == 0) ? Wq : (z == 1) ? Wk : Wv;
    const float* B = (z == 0) ? bq : (z == 1) ? bk : bv;
    float*       C = (z == 0) ? Qg : (z == 1) ? Kg : Vg;
    gemm_body(A, W, B, C, MTOT, EDIM, EDIM, 1);
}

__global__ __launch_bounds__(256) void gemm_out(
    const float* __restrict__ A, const float* __restrict__ W,
    const float* __restrict__ bias, float* __restrict__ C)
{
    gemm_body(A, W, bias, C, MTOT, EDIM, EDIM, 0);
}

// ============================================================
// Rel projection (tf32-rounded output)
// ============================================================
__global__ __launch_bounds__(256) void relproj2_kernel(
    const float* __restrict__ rel_emb, const float* __restrict__ Wp,
    float* __restrict__ Rk)
{
    __shared__ float sWT[HD*HD];
    __shared__ float sR[32*HD];
    const int tid = threadIdx.x;
    const int r0 = blockIdx.x * 32;
    const int rows = (NREL - r0) < 32 ? (NREL - r0) : 32;
    for (int i = tid; i < HD*HD; i += 256) {
        int d = i >> 6, k = i & 63;
        sWT[k*HD + d] = Wp[i];
    }
    for (int i = tid; i < rows*HD; i += 256)
        sR[i] = rel_emb[(size_t)r0*HD + i];
    __syncthreads();
    for (int o = tid; o < rows*HD; o += 256) {
        int rl = o >> 6, d = o & 63;
        float acc = 0.f;
#pragma unroll 16
        for (int k = 0; k < HD; k++)
            acc += sR[rl*HD + k] * sWT[k*HD + d];
        Rk[(size_t)(r0 + rl)*HD + d] = __uint_as_float(f2tf32(acc));
    }
}

// ============================================================
// Flash attention v4: 512 threads / 16 warps, TF32 MMA,
// cp.async double-buffer (K/V/Rk/mask), per-warp 16x16 sub-blocks.
// ============================================================
#define FP 68
#define SM_KS   0
#define SM_VS   (SM_KS + 2*64*FP)
#define SM_RK   (SM_VS + 2*64*FP)
#define SM_POS  (SM_RK + 2*128*FP)        // aliases: Q staging, pos, O-partial A
#define SM_PSW  (SM_POS + 64*FP)          // per-warp P staging 16x20; O-partial B
#define SM_MSK  (SM_PSW + 16*16*20)
#define SM_PSUM (SM_MSK + 2048)
#define FLASH_SMEM ((SM_PSUM + 256) * 4)  // 186368 bytes

__global__ __launch_bounds__(512) void flash_rel_mma(
    const float* __restrict__ Q, const float* __restrict__ K,
    const float* __restrict__ V, const unsigned char* __restrict__ mask,
    const float* __restrict__ Rk, float* __restrict__ O)
{
    extern __shared__ uint32_t su[];
    uint32_t* Ks   = su + SM_KS;
    uint32_t* Vs   = su + SM_VS;
    uint32_t* RkB  = su + SM_RK;
    uint32_t* PosU = su + SM_POS;
    float*    PosS = (float*)PosU;
    float*    psum = (float*)(su + SM_PSUM);
    unsigned char* MskB = (unsigned char*)(su + SM_MSK);

    const int tid  = threadIdx.x;
    const int lane = tid & 31, warp = tid >> 5;
    const int g    = lane >> 2, tg = lane & 3;
    const int wm   = warp >> 2, wn = warp & 3;   // 4x4 warp grid
    const int b    = blockIdx.z, h = blockIdx.y;
    const int i0   = blockIdx.x << 6;
    const int rb   = wm << 4;
    const float scale = 0.125f;

    uint32_t* PsW = su + SM_PSW + warp*320;      // 16 rows x 20 words

    const uint32_t sK   = (uint32_t)__cvta_generic_to_shared(Ks);
    const uint32_t sV   = (uint32_t)__cvta_generic_to_shared(Vs);
    const uint32_t sR   = (uint32_t)__cvta_generic_to_shared(RkB);
    const uint32_t sPos = (uint32_t)__cvta_generic_to_shared(PosU);
    const uint32_t sM   = (uint32_t)__cvta_generic_to_shared(MskB);

    const unsigned char* mbase = mask + (size_t)b*SEQ*SEQ + (size_t)i0*SEQ;

    auto issue_tile = [&](int j0, int buf) {
        const float* Kb = K + ((size_t)(b*SEQ + j0)) * EDIM + h*HD;
        const float* Vb = V + ((size_t)(b*SEQ + j0)) * EDIM + h*HD;
        const uint32_t kdst = sK + (uint32_t)buf*64*FP*4;
        const uint32_t vdst = sV + (uint32_t)buf*64*FP*4;
        for (int e = tid; e < 1024; e += 512) {
            int row = e >> 4, c4 = (e & 15) << 2;
            cpa16(kdst + (row*FP + c4)*4, Kb + (size_t)row*EDIM + c4);
            cpa16(vdst + (row*FP + c4)*4, Vb + (size_t)row*EDIM + c4);
        }
        const int r0 = j0 - i0 + (SEQ - 1);
        const float* Rb = Rk + (size_t)(r0 - 63)*HD;
        const uint32_t rdst = sR + (uint32_t)buf*128*FP*4;
        for (int e = tid; e < 127*16; e += 512) {
            int u = e >> 4, c4 = (e & 15) << 2;
            cpa16(rdst + (u*FP + c4)*4, Rb + (size_t)u*HD + c4);
        }
        // mask tile 64x64 bytes
        if (tid < 256) {
            int row = tid >> 2, ch = (tid & 3) << 4;
            cpa16(sM + buf*4096 + row*64 + ch, mbase + (size_t)row*SEQ + j0 + ch);
        }
    };

    // prologue: Q staged into PosS region + tile 0
    const float* Qbase = Q + ((size_t)(b*SEQ + i0)) * EDIM + h*HD;
    for (int e = tid; e < 1024; e += 512) {
        int row = e >> 4, c4 = (e & 15) << 2;
        cpa16(sPos + (row*FP + c4)*4, Qbase + (size_t)row*EDIM + c4);
    }
    issue_tile(0, 0);
    cpa_commit();
    cpa_wait_all();
    __syncthreads();

    const int rowA = rb + g, rowB = rowA + 8;
    uint32_t qf[8][4];
#pragma unroll
    for (int k8 = 0; k8 < 8; k8++) {
        int kk = k8 << 3;
        qf[k8][0] = PosU[rowA*FP + kk + tg];
        qf[k8][1] = PosU[rowB*FP + kk + tg];
        qf[k8][2] = PosU[rowA*FP + kk + tg + 4];
        qf[k8][3] = PosU[rowB*FP + kk + tg + 4];
    }
    issue_tile(64, 1);
    cpa_commit();
    __syncthreads();   // Q consumed before PosS overwritten

    float oacc[8][4];
#pragma unroll
    for (int c = 0; c < 8; c++)
#pragma unroll
        for (int q = 0; q < 4; q++) oacc[c][q] = 0.f;
    float l_lo = 0.f, l_hi = 0.f;

    const int ubase = 48 - rb + 20*wn;   // pos band start for this warp

    for (int kt = 0; kt < NT; kt++) {
        const int buf = kt & 1;
        if (kt > 0) {
            cpa_wait_all();
            __syncthreads();
            if (kt + 1 < NT) { issue_tile((kt+1) << 6, (kt+1) & 1); cpa_commit(); }
        }

        const uint32_t* KsB = Ks  + buf*64*FP;
        const uint32_t* VsB = Vs  + buf*64*FP;
        const uint32_t* RkT = RkB + buf*128*FP;

        // ---- S MMAs: content (2 frags) + pos band (3 frags) ----
        float ca[2][4], pa[3][4];
#pragma unroll
        for (int c = 0; c < 2; c++)
#pragma unroll
            for (int q = 0; q < 4; q++) ca[c][q] = 0.f;
#pragma unroll
        for (int c = 0; c < 3; c++)
#pragma unroll
            for (int q = 0; q < 4; q++) pa[c][q] = 0.f;

#pragma unroll
        for (int k8 = 0; k8 < 8; k8++) {
            int kk = k8 << 3;
#pragma unroll
            for (int c = 0; c < 2; c++) {
                int n = (wn << 4) + (c << 3);
                uint32_t b0 = KsB[(n + g)*FP + kk + tg];
                uint32_t b1 = KsB[(n + g)*FP + kk + tg + 4];
                MMA_TF32(ca[c], qf[k8][0], qf[k8][1], qf[k8][2], qf[k8][3], b0, b1);
            }
#pragma unroll
            for (int c = 0; c < 3; c++) {
                int u = ubase + (c << 3);
                uint32_t b0 = RkT[(u + g)*FP + kk + tg];
                uint32_t b1 = RkT[(u + g)*FP + kk + tg + 4];
                MMA_TF32(pa[c], qf[k8][0], qf[k8][1], qf[k8][2], qf[k8][3], b0, b1);
            }
        }

        // scatter pos diagonally: PosS[row][u + row - 63]
#pragma unroll
        for (int c = 0; c < 3; c++) {
            int u2 = ubase + (c << 3) + (tg << 1);
            int jA = u2 + rowA - 63;
            if (jA   >= 0 && jA   < 64) PosS[rowA*FP + jA    ] = pa[c][0];
            if (jA+1 >= 0 && jA+1 < 64) PosS[rowA*FP + jA + 1] = pa[c][1];
            int jB = u2 + rowB - 63;
            if (jB   >= 0 && jB   < 64) PosS[rowB*FP + jB    ] = pa[c][2];
            if (jB+1 >= 0 && jB+1 < 64) PosS[rowB*FP + jB + 1] = pa[c][3];
        }
        __syncthreads();

        // ---- softmax (no-max) + P staging (smem mask) ----
        const unsigned char* mT = MskB + buf*4096;
#pragma unroll
        for (int c = 0; c < 2; c++) {
            int col  = (wn << 4) + (c << 3) + (tg << 1);
            int colL = (c << 3) + (tg << 1);
            uchar2 ma = *(const uchar2*)(mT + rowA*64 + col);
            uchar2 mb = *(const uchar2*)(mT + rowB*64 + col);
            float p0 = ma.x ? 0.f : __expf(scale*(ca[c][0] + PosS[rowA*FP + col    ]));
            float p1 = ma.y ? 0.f : __expf(scale*(ca[c][1] + PosS[rowA*FP + col + 1]));
            float p2 = mb.x ? 0.f : __expf(scale*(ca[c][2] + PosS[rowB*FP + col    ]));
            float p3 = mb.y ? 0.f : __expf(scale*(ca[c][3] + PosS[rowB*FP + col + 1]));
            l_lo += p0 + p1;
            l_hi += p2 + p3;
            *(uint2*)(PsW + g*20      + colL) = make_uint2(f2tf32(p0), f2tf32(p1));
            *(uint2*)(PsW + (g+8)*20  + colL) = make_uint2(f2tf32(p2), f2tf32(p3));
        }
        __syncwarp();

        // ---- PV over this warp's own 16-j slice, all 64 n-cols ----
#pragma unroll
        for (int k4 = 0; k4 < 2; k4++) {
            int kk = k4 << 3;
            uint32_t a0 = PsW[g*20     + kk + tg];
            uint32_t a1 = PsW[(g+8)*20 + kk + tg];
            uint32_t a2 = PsW[g*20     + kk + tg + 4];
            uint32_t a3 = PsW[(g+8)*20 + kk + tg + 4];
            int jr = (wn << 4) + kk + tg;
#pragma unroll
            for (int c = 0; c < 8; c++) {
                int n = c << 3;
                uint32_t b0 = VsB[(jr    )*FP + n + g];
                uint32_t b1 = VsB[(jr + 4)*FP + n + g];
                MMA_TF32(oacc[c], a0, a1, a2, a3, b0, b1);
            }
        }
    }

    // ---- l reductions ----
    l_lo += __shfl_xor_sync(0xffffffffu, l_lo, 1);
    l_lo += __shfl_xor_sync(0xffffffffu, l_lo, 2);
    l_hi += __shfl_xor_sync(0xffffffffu, l_hi, 1);
    l_hi += __shfl_xor_sync(0xffffffffu, l_hi, 2);
    if (tg == 0) {
        psum[(wn << 6) + rowA] = l_lo;
        psum[(wn << 6) + rowB] = l_hi;
    }
    __syncthreads();

    // ---- 4-way O partial reduction (tree via PosS & PSW regions) ----
    float* BufA = PosS;                       // [64][FP]
    float* BufB = (float*)(su + SM_PSW);      // [64][FP] (5120 >= 4352 words)

    if (wn == 1 || wn == 3) {
        float* dst = (wn == 1) ? BufA : BufB;
#pragma unroll
        for (int c = 0; c < 8; c++) {
            int col = (c << 3) + (tg << 1);
            *(float2*)(dst + rowA*FP + col) = make_float2(oacc[c][0], oacc[c][1]);
            *(float2*)(dst + rowB*FP + col) = make_float2(oacc[c][2], oacc[c][3]);
        }
    }
    __syncthreads();
    if (wn == 0 || wn == 2) {
        float* srcp = (wn == 0) ? BufA : BufB;
#pragma unroll
        for (int c = 0; c < 8; c++) {
            int col = (c << 3) + (tg << 1);
            float2 vA = *(float2*)(srcp + rowA*FP + col);
            float2 vB = *(float2*)(srcp + rowB*FP + col);
            oacc[c][0] += vA.x; oacc[c][1] += vA.y;
            oacc[c][2] += vB.x; oacc[c][3] += vB.y;
        }
    }
    __syncthreads();
    if (wn == 2) {
#pragma unroll
        for (int c = 0; c < 8; c++) {
            int col = (c << 3) + (tg << 1);
            *(float2*)(BufA + rowA*FP + col) = make_float2(oacc[c][0], oacc[c][1]);
            *(float2*)(BufA + rowB*FP + col) = make_float2(oacc[c][2], oacc[c][3]);
        }
    }
    __syncthreads();
    if (wn == 0) {
        float lA = psum[rowA] + psum[64 + rowA] + psum[128 + rowA] + psum[192 + rowA];
        float lB = psum[rowB] + psum[64 + rowB] + psum[128 + rowB] + psum[192 + rowB];
        float invA = 1.f / lA, invB = 1.f / lB;
        float* ObA = O + ((size_t)(b*SEQ + i0 + rowA)) * EDIM + h*HD;
        float* ObB = O + ((size_t)(b*SEQ + i0 + rowB)) * EDIM + h*HD;
#pragma unroll
        for (int c = 0; c < 8; c++) {
            int col = (c << 3) + (tg << 1);
            float2 vA = *(float2*)(BufA + rowA*FP + col);
            float2 vB = *(float2*)(BufA + rowB*FP + col);
            *(float2*)(ObA + col) = make_float2((oacc[c][0] + vA.x) * invA,
                                                (oacc[c][1] + vA.y) * invA);
            *(float2*)(ObB + col) = make_float2((oacc[c][2] + vB.x) * invB,
                                                (oacc[c][3] + vB.y) * invB);
        }
    }
}

// ============================================================
extern "C" void kernel_launch(void* const* d_in, const int* in_sizes, int n_in,
                              void* d_out, int out_size)
{
    const float* query = (const float*)d_in[0];
    const float* key_  = (const float*)d_in[1];
    const float* value = (const float*)d_in[2];
    const unsigned char* mask = (const unsigned char*)d_in[3];
    const float* Wq = (const float*)d_in[4];
    const float* bq = (const float*)d_in[5];
    const float* Wk = (const float*)d_in[6];
    const float* bk = (const float*)d_in[7];
    const float* Wv = (const float*)d_in[8];
    const float* bv = (const float*)d_in[9];
    const float* Wo = (const float*)d_in[10];
    const float* bo = (const float*)d_in[11];
    const float* rel_emb = (const float*)d_in[12];
    const float* Wp = (const float*)d_in[13];
    float* out = (float*)d_out;

    float *Qg, *Kg, *Vg, *Cg, *Rkg;
    cudaGetSymbolAddress((void**)&Qg,  g_Q);
    cudaGetSymbolAddress((void**)&Kg,  g_K);
    cudaGetSymbolAddress((void**)&Vg,  g_V);
    cudaGetSymbolAddress((void**)&Cg,  g_ctx);
    cudaGetSymbolAddress((void**)&Rkg, g_Rk);

    cudaFuncSetAttribute(gemm_qkv,
                         cudaFuncAttributeMaxDynamicSharedMemorySize, GEMM_SMEM);
    cudaFuncSetAttribute(gemm_out,
                         cudaFuncAttributeMaxDynamicSharedMemorySize, GEMM_SMEM);
    cudaFuncSetAttribute(flash_rel_mma,
                         cudaFuncAttributeMaxDynamicSharedMemorySize, FLASH_SMEM);

    dim3 gblk(256);

    dim3 gq(EDIM/128, MTOT/128, 3);
    gemm_qkv<<<gq, gblk, GEMM_SMEM>>>(query, key_, value, Wq, Wk, Wv,
                                      bq, bk, bv, Qg, Kg, Vg);
    relproj2_kernel<<<(NREL + 31)/32, 256>>>(rel_emb, Wp, Rkg);

    dim3 fgrid(SEQ/64, NH, BATCH);
    flash_rel_mma<<<fgrid, 512, FLASH_SMEM>>>(Qg, Kg, Vg, mask, Rkg, Cg);

    dim3 go(EDIM/128, MTOT/128, 1);
    gemm_out<<<go, gblk, GEMM_SMEM>>>(Cg, Wo, bo, out);
}

// round 15
// speedup vs baseline: 1.0011x; 1.0011x over previous
#include <cuda_runtime.h>
#include <math.h>
#include <stdint.h>

#define EDIM 1024
#define NH   16
#define HD   64
#define BATCH 4
#define SEQ  1024
#define MTOT (BATCH*SEQ)      // 4096
#define NREL (2*SEQ - 1)      // 2047
#define NT   (SEQ/64)         // 16 k-tiles

// ---- scratch ----
__device__ float g_Q[MTOT*EDIM];
__device__ float g_K[MTOT*EDIM];
__device__ float g_V[MTOT*EDIM];
__device__ float g_ctx[MTOT*EDIM];
__device__ float g_Rk[NREL*HD];

__device__ __forceinline__ uint32_t f2tf32(float f) {
    uint32_t u;
    asm("cvt.rna.tf32.f32 %0, %1;" : "=r"(u) : "f"(f));
    return u;
}

#define MMA_TF32(acc, A0, A1, A2, A3, B0, B1)                                \
    asm volatile(                                                            \
        "mma.sync.aligned.m16n8k8.row.col.f32.tf32.tf32.f32 "               \
        "{%0,%1,%2,%3}, {%4,%5,%6,%7}, {%8,%9}, {%0,%1,%2,%3};"             \
        : "+f"((acc)[0]), "+f"((acc)[1]), "+f"((acc)[2]), "+f"((acc)[3])     \
        : "r"(A0), "r"(A1), "r"(A2), "r"(A3), "r"(B0), "r"(B1))

__device__ __forceinline__ void cpa16(uint32_t dst, const void* src) {
    asm volatile("cp.async.cg.shared.global [%0], [%1], 16;" :: "r"(dst), "l"(src));
}
__device__ __forceinline__ void cpa_commit() {
    asm volatile("cp.async.commit_group;");
}
__device__ __forceinline__ void cpa_wait_all() {
    asm volatile("cp.async.wait_group 0;" ::: "memory");
}

// ============================================================
// TF32 GEMM body (unchanged): C = A @ W^T + bias
// ============================================================
#define KC  32
#define PAD 36
#define GEMM_SMEM (2*2*128*PAD*4)   // 73728 bytes

__device__ __forceinline__ void gemm_body(
    const float* __restrict__ A, const float* __restrict__ W,
    const float* __restrict__ bias, float* __restrict__ C,
    int M, int N, int K, int round_out)
{
    extern __shared__ float smf[];
    uint32_t* As = (uint32_t*)smf;
    uint32_t* Bs = As + 2*128*PAD;

    const int tid  = threadIdx.x;
    const int lane = tid & 31;
    const int warp = tid >> 5;
    const int g    = lane >> 2;
    const int tig  = lane & 3;
    const int wm   = warp >> 2;
    const int wn   = warp & 3;
    const int bm   = blockIdx.y << 7;
    const int bn   = blockIdx.x << 7;

    const int r0 = tid >> 3;
    const int c4 = tid & 7;

    const float* Ap = A + (size_t)(bm + r0) * K + (c4 << 2);
    const float* Wp = W + (size_t)(bn + r0) * K + (c4 << 2);

    float acc[4][4][4];
#pragma unroll
    for (int mi = 0; mi < 4; mi++)
#pragma unroll
        for (int ni = 0; ni < 4; ni++)
#pragma unroll
            for (int q = 0; q < 4; q++) acc[mi][ni][q] = 0.f;

    float4 ra[4], rw[4];
    const int nt = K / KC;

#pragma unroll
    for (int i = 0; i < 4; i++) {
        ra[i] = *(const float4*)(Ap + (size_t)(i*32) * K);
        rw[i] = *(const float4*)(Wp + (size_t)(i*32) * K);
    }
    {
        uint32_t* dA = As;
        uint32_t* dB = Bs;
#pragma unroll
        for (int i = 0; i < 4; i++) {
            int off = (r0 + i*32)*PAD + (c4 << 2);
            dA[off+0] = f2tf32(ra[i].x); dA[off+1] = f2tf32(ra[i].y);
            dA[off+2] = f2tf32(ra[i].z); dA[off+3] = f2tf32(ra[i].w);
            dB[off+0] = f2tf32(rw[i].x); dB[off+1] = f2tf32(rw[i].y);
            dB[off+2] = f2tf32(rw[i].z); dB[off+3] = f2tf32(rw[i].w);
        }
    }

    for (int kt = 0; kt < nt; kt++) {
        __syncthreads();
        if (kt + 1 < nt) {
            const float* Ap2 = Ap + (size_t)(kt+1)*KC;
            const float* Wp2 = Wp + (size_t)(kt+1)*KC;
#pragma unroll
            for (int i = 0; i < 4; i++) {
                ra[i] = *(const float4*)(Ap2 + (size_t)(i*32) * K);
                rw[i] = *(const float4*)(Wp2 + (size_t)(i*32) * K);
            }
        }

        const uint32_t* cA = As + (kt & 1) * 128*PAD;
        const uint32_t* cB = Bs + (kt & 1) * 128*PAD;

#pragma unroll
        for (int kk = 0; kk < KC; kk += 8) {
            uint32_t af[4][4], bf[4][2];
#pragma unroll
            for (int mi = 0; mi < 4; mi++) {
                int r = (wm << 6) + (mi << 4);
                af[mi][0] = cA[(r + g    )*PAD + kk + tig    ];
                af[mi][1] = cA[(r + g + 8)*PAD + kk + tig    ];
                af[mi][2] = cA[(r + g    )*PAD + kk + tig + 4];
                af[mi][3] = cA[(r + g + 8)*PAD + kk + tig + 4];
            }
#pragma unroll
            for (int ni = 0; ni < 4; ni++) {
                int cn = (wn << 5) + (ni << 3);
                bf[ni][0] = cB[(cn + g)*PAD + kk + tig    ];
                bf[ni][1] = cB[(cn + g)*PAD + kk + tig + 4];
            }
#pragma unroll
            for (int mi = 0; mi < 4; mi++)
#pragma unroll
                for (int ni = 0; ni < 4; ni++)
                    MMA_TF32(acc[mi][ni], af[mi][0], af[mi][1], af[mi][2], af[mi][3],
                             bf[ni][0], bf[ni][1]);
        }

        if (kt + 1 < nt) {
            uint32_t* dA = As + ((kt+1) & 1) * 128*PAD;
            uint32_t* dB = Bs + ((kt+1) & 1) * 128*PAD;
#pragma unroll
            for (int i = 0; i < 4; i++) {
                int off = (r0 + i*32)*PAD + (c4 << 2);
                dA[off+0] = f2tf32(ra[i].x); dA[off+1] = f2tf32(ra[i].y);
                dA[off+2] = f2tf32(ra[i].z); dA[off+3] = f2tf32(ra[i].w);
                dB[off+0] = f2tf32(rw[i].x); dB[off+1] = f2tf32(rw[i].y);
                dB[off+2] = f2tf32(rw[i].z); dB[off+3] = f2tf32(rw[i].w);
            }
        }
    }

#pragma unroll
    for (int mi = 0; mi < 4; mi++) {
        int row = bm + (wm << 6) + (mi << 4) + g;
#pragma unroll
        for (int ni = 0; ni < 4; ni++) {
            int col = bn + (wn << 5) + (ni << 3) + (tig << 1);
            float b0 = bias[col], b1 = bias[col + 1];
            float v0 = acc[mi][ni][0] + b0, v1 = acc[mi][ni][1] + b1;
            float v2 = acc[mi][ni][2] + b0, v3 = acc[mi][ni][3] + b1;
            if (round_out) {
                v0 = __uint_as_float(f2tf32(v0));
                v1 = __uint_as_float(f2tf32(v1));
                v2 = __uint_as_float(f2tf32(v2));
                v3 = __uint_as_float(f2tf32(v3));
            }
            *(float2*)(C + (size_t)row       * N + col) = make_float2(v0, v1);
            *(float2*)(C + (size_t)(row + 8) * N + col) = make_float2(v2, v3);
        }
    }
}

__global__ __launch_bounds__(256) void gemm_qkv(
    const float* __restrict__ q, const float* __restrict__ k,
    const float* __restrict__ v,
    const float* __restrict__ Wq, const float* __restrict__ Wk,
    const float* __restrict__ Wv,
    const float* __restrict__ bq, const float* __restrict__ bk,
    const float* __restrict__ bv,
    float* __restrict__ Qg, float* __restrict__ Kg, float* __restrict__ Vg)
{
    const int z = blockIdx.z;
    const float* A = (z == 0) ? q  : (z == 1) ? k  : v;
    const float* W = (z == 0) ? Wq : (z == 1) ? Wk : Wv;
    const float* B = (z == 0) ? bq : (z == 1) ? bk : bv;
    float*       C = (z == 0) ? Qg : (z == 1) ? Kg : Vg;
    gemm_body(A, W, B, C, MTOT, EDIM, EDIM, 1);
}

__global__ __launch_bounds__(256) void gemm_out(
    const float* __restrict__ A, const float* __restrict__ W,
    const float* __restrict__ bias, float* __restrict__ C)
{
    gemm_body(A, W, bias, C, MTOT, EDIM, EDIM, 0);
}

// ============================================================
// Rel projection (tf32-rounded output)
// ============================================================
__global__ __launch_bounds__(256) void relproj2_kernel(
    const float* __restrict__ rel_emb, const float* __restrict__ Wp,
    float* __restrict__ Rk)
{
    __shared__ float sWT[HD*HD];
    __shared__ float sR[32*HD];
    const int tid = threadIdx.x;
    const int r0 = blockIdx.x * 32;
    const int rows = (NREL - r0) < 32 ? (NREL - r0) : 32;
    for (int i = tid; i < HD*HD; i += 256) {
        int d = i >> 6, k = i & 63;
        sWT[k*HD + d] = Wp[i];
    }
    for (int i = tid; i < rows*HD; i += 256)
        sR[i] = rel_emb[(size_t)r0*HD + i];
    __syncthreads();
    for (int o = tid; o < rows*HD; o += 256) {
        int rl = o >> 6, d = o & 63;
        float acc = 0.f;
#pragma unroll 16
        for (int k = 0; k < HD; k++)
            acc += sR[rl*HD + k] * sWT[k*HD + d];
        Rk[(size_t)(r0 + rl)*HD + d] = __uint_as_float(f2tf32(acc));
    }
}

// ============================================================
// Flash attention v4: 512 threads / 16 warps, TF32 MMA,
// cp.async double-buffer (K/V/Rk/mask), per-warp 16x16 sub-blocks.
// ============================================================
#define FP 68
#define SM_KS   0
#define SM_VS   (SM_KS + 2*64*FP)
#define SM_RK   (SM_VS + 2*64*FP)
#define SM_POS  (SM_RK + 2*128*FP)        // aliases: Q staging, pos, O-partial A
#define SM_PSW  (SM_POS + 64*FP)          // per-warp P staging 16x20; O-partial B
#define SM_MSK  (SM_PSW + 16*16*20)
#define SM_PSUM (SM_MSK + 2048)
#define FLASH_SMEM ((SM_PSUM + 256) * 4)  // 186368 bytes

__global__ __launch_bounds__(512) void flash_rel_mma(
    const float* __restrict__ Q, const float* __restrict__ K,
    const float* __restrict__ V, const unsigned char* __restrict__ mask,
    const float* __restrict__ Rk, float* __restrict__ O)
{
    extern __shared__ uint32_t su[];
    uint32_t* Ks   = su + SM_KS;
    uint32_t* Vs   = su + SM_VS;
    uint32_t* RkB  = su + SM_RK;
    uint32_t* PosU = su + SM_POS;
    float*    PosS = (float*)PosU;
    float*    psum = (float*)(su + SM_PSUM);
    unsigned char* MskB = (unsigned char*)(su + SM_MSK);

    const int tid  = threadIdx.x;
    const int lane = tid & 31, warp = tid >> 5;
    const int g    = lane >> 2, tg = lane & 3;
    const int wm   = warp >> 2, wn = warp & 3;   // 4x4 warp grid
    const int b    = blockIdx.z, h = blockIdx.y;
    const int i0   = blockIdx.x << 6;
    const int rb   = wm << 4;
    const float scale = 0.125f;

    uint32_t* PsW = su + SM_PSW + warp*320;      // 16 rows x 20 words

    const uint32_t sK   = (uint32_t)__cvta_generic_to_shared(Ks);
    const uint32_t sV   = (uint32_t)__cvta_generic_to_shared(Vs);
    const uint32_t sR   = (uint32_t)__cvta_generic_to_shared(RkB);
    const uint32_t sPos = (uint32_t)__cvta_generic_to_shared(PosU);
    const uint32_t sM   = (uint32_t)__cvta_generic_to_shared(MskB);

    const unsigned char* mbase = mask + (size_t)b*SEQ*SEQ + (size_t)i0*SEQ;

    auto issue_tile = [&](int j0, int buf) {
        const float* Kb = K + ((size_t)(b*SEQ + j0)) * EDIM + h*HD;
        const float* Vb = V + ((size_t)(b*SEQ + j0)) * EDIM + h*HD;
        const uint32_t kdst = sK + (uint32_t)buf*64*FP*4;
        const uint32_t vdst = sV + (uint32_t)buf*64*FP*4;
        for (int e = tid; e < 1024; e += 512) {
            int row = e >> 4, c4 = (e & 15) << 2;
            cpa16(kdst + (row*FP + c4)*4, Kb + (size_t)row*EDIM + c4);
            cpa16(vdst + (row*FP + c4)*4, Vb + (size_t)row*EDIM + c4);
        }
        const int r0 = j0 - i0 + (SEQ - 1);
        const float* Rb = Rk + (size_t)(r0 - 63)*HD;
        const uint32_t rdst = sR + (uint32_t)buf*128*FP*4;
        for (int e = tid; e < 127*16; e += 512) {
            int u = e >> 4, c4 = (e & 15) << 2;
            cpa16(rdst + (u*FP + c4)*4, Rb + (size_t)u*HD + c4);
        }
        // mask tile 64x64 bytes
        if (tid < 256) {
            int row = tid >> 2, ch = (tid & 3) << 4;
            cpa16(sM + buf*4096 + row*64 + ch, mbase + (size_t)row*SEQ + j0 + ch);
        }
    };

    // prologue: Q staged into PosS region + tile 0
    const float* Qbase = Q + ((size_t)(b*SEQ + i0)) * EDIM + h*HD;
    for (int e = tid; e < 1024; e += 512) {
        int row = e >> 4, c4 = (e & 15) << 2;
        cpa16(sPos + (row*FP + c4)*4, Qbase + (size_t)row*EDIM + c4);
    }
    issue_tile(0, 0);
    cpa_commit();
    cpa_wait_all();
    __syncthreads();

    const int rowA = rb + g, rowB = rowA + 8;
    uint32_t qf[8][4];
#pragma unroll
    for (int k8 = 0; k8 < 8; k8++) {
        int kk = k8 << 3;
        qf[k8][0] = PosU[rowA*FP + kk + tg];
        qf[k8][1] = PosU[rowB*FP + kk + tg];
        qf[k8][2] = PosU[rowA*FP + kk + tg + 4];
        qf[k8][3] = PosU[rowB*FP + kk + tg + 4];
    }
    issue_tile(64, 1);
    cpa_commit();
    __syncthreads();   // Q consumed before PosS overwritten

    float oacc[8][4];
#pragma unroll
    for (int c = 0; c < 8; c++)
#pragma unroll
        for (int q = 0; q < 4; q++) oacc[c][q] = 0.f;
    float l_lo = 0.f, l_hi = 0.f;

    const int ubase = 48 - rb + 20*wn;   // pos band start for this warp

    for (int kt = 0; kt < NT; kt++) {
        const int buf = kt & 1;
        if (kt > 0) {
            cpa_wait_all();
            __syncthreads();
            if (kt + 1 < NT) { issue_tile((kt+1) << 6, (kt+1) & 1); cpa_commit(); }
        }

        const uint32_t* KsB = Ks  + buf*64*FP;
        const uint32_t* VsB = Vs  + buf*64*FP;
        const uint32_t* RkT = RkB + buf*128*FP;

        // ---- S MMAs: content (2 frags) + pos band (3 frags) ----
        float ca[2][4], pa[3][4];
#pragma unroll
        for (int c = 0; c < 2; c++)
#pragma unroll
            for (int q = 0; q < 4; q++) ca[c][q] = 0.f;
#pragma unroll
        for (int c = 0; c < 3; c++)
#pragma unroll
            for (int q = 0; q < 4; q++) pa[c][q] = 0.f;

#pragma unroll
        for (int k8 = 0; k8 < 8; k8++) {
            int kk = k8 << 3;
#pragma unroll
            for (int c = 0; c < 2; c++) {
                int n = (wn << 4) + (c << 3);
                uint32_t b0 = KsB[(n + g)*FP + kk + tg];
                uint32_t b1 = KsB[(n + g)*FP + kk + tg + 4];
                MMA_TF32(ca[c], qf[k8][0], qf[k8][1], qf[k8][2], qf[k8][3], b0, b1);
            }
#pragma unroll
            for (int c = 0; c < 3; c++) {
                int u = ubase + (c << 3);
                uint32_t b0 = RkT[(u + g)*FP + kk + tg];
                uint32_t b1 = RkT[(u + g)*FP + kk + tg + 4];
                MMA_TF32(pa[c], qf[k8][0], qf[k8][1], qf[k8][2], qf[k8][3], b0, b1);
            }
        }

        // scatter pos diagonally: PosS[row][u + row - 63]
#pragma unroll
        for (int c = 0; c < 3; c++) {
            int u2 = ubase + (c << 3) + (tg << 1);
            int jA = u2 + rowA - 63;
            if (jA   >= 0 && jA   < 64) PosS[rowA*FP + jA    ] = pa[c][0];
            if (jA+1 >= 0 && jA+1 < 64) PosS[rowA*FP + jA + 1] = pa[c][1];
            int jB = u2 + rowB - 63;
            if (jB   >= 0 && jB   < 64) PosS[rowB*FP + jB    ] = pa[c][2];
            if (jB+1 >= 0 && jB+1 < 64) PosS[rowB*FP + jB + 1] = pa[c][3];
        }
        __syncthreads();

        // ---- softmax (no-max) + P staging (smem mask) ----
        const unsigned char* mT = MskB + buf*4096;
#pragma unroll
        for (int c = 0; c < 2; c++) {
            int col  = (wn << 4) + (c << 3) + (tg << 1);
            int colL = (c << 3) + (tg << 1);
            uchar2 ma = *(const uchar2*)(mT + rowA*64 + col);
            uchar2 mb = *(const uchar2*)(mT + rowB*64 + col);
            float p0 = ma.x ? 0.f : __expf(scale*(ca[c][0] + PosS[rowA*FP + col    ]));
            float p1 = ma.y ? 0.f : __expf(scale*(ca[c][1] + PosS[rowA*FP + col + 1]));
            float p2 = mb.x ? 0.f : __expf(scale*(ca[c][2] + PosS[rowB*FP + col    ]));
            float p3 = mb.y ? 0.f : __expf(scale*(ca[c][3] + PosS[rowB*FP + col + 1]));
            l_lo += p0 + p1;
            l_hi += p2 + p3;
            *(uint2*)(PsW + g*20      + colL) = make_uint2(f2tf32(p0), f2tf32(p1));
            *(uint2*)(PsW + (g+8)*20  + colL) = make_uint2(f2tf32(p2), f2tf32(p3));
        }
        __syncwarp();

        // ---- PV over this warp's own 16-j slice, all 64 n-cols ----
#pragma unroll
        for (int k4 = 0; k4 < 2; k4++) {
            int kk = k4 << 3;
            uint32_t a0 = PsW[g*20     + kk + tg];
            uint32_t a1 = PsW[(g+8)*20 + kk + tg];
            uint32_t a2 = PsW[g*20     + kk + tg + 4];
            uint32_t a3 = PsW[(g+8)*20 + kk + tg + 4];
            int jr = (wn << 4) + kk + tg;
#pragma unroll
            for (int c = 0; c < 8; c++) {
                int n = c << 3;
                uint32_t b0 = VsB[(jr    )*FP + n + g];
                uint32_t b1 = VsB[(jr + 4)*FP + n + g];
                MMA_TF32(oacc[c], a0, a1, a2, a3, b0, b1);
            }
        }
    }

    // ---- l reductions ----
    l_lo += __shfl_xor_sync(0xffffffffu, l_lo, 1);
    l_lo += __shfl_xor_sync(0xffffffffu, l_lo, 2);
    l_hi += __shfl_xor_sync(0xffffffffu, l_hi, 1);
    l_hi += __shfl_xor_sync(0xffffffffu, l_hi, 2);
    if (tg == 0) {
        psum[(wn << 6) + rowA] = l_lo;
        psum[(wn << 6) + rowB] = l_hi;
    }
    __syncthreads();

    // ---- 4-way O partial reduction (tree via PosS & PSW regions) ----
    float* BufA = PosS;                       // [64][FP]
    float* BufB = (float*)(su + SM_PSW);      // [64][FP] (5120 >= 4352 words)

    if (wn == 1 || wn == 3) {
        float* dst = (wn == 1) ? BufA : BufB;
#pragma unroll
        for (int c = 0; c < 8; c++) {
            int col = (c << 3) + (tg << 1);
            *(float2*)(dst + rowA*FP + col) = make_float2(oacc[c][0], oacc[c][1]);
            *(float2*)(dst + rowB*FP + col) = make_float2(oacc[c][2], oacc[c][3]);
        }
    }
    __syncthreads();
    if (wn == 0 || wn == 2) {
        float* srcp = (wn == 0) ? BufA : BufB;
#pragma unroll
        for (int c = 0; c < 8; c++) {
            int col = (c << 3) + (tg << 1);
            float2 vA = *(float2*)(srcp + rowA*FP + col);
            float2 vB = *(float2*)(srcp + rowB*FP + col);
            oacc[c][0] += vA.x; oacc[c][1] += vA.y;
            oacc[c][2] += vB.x; oacc[c][3] += vB.y;
        }
    }
    __syncthreads();
    if (wn == 2) {
#pragma unroll
        for (int c = 0; c < 8; c++) {
            int col = (c << 3) + (tg << 1);
            *(float2*)(BufA + rowA*FP + col) = make_float2(oacc[c][0], oacc[c][1]);
            *(float2*)(BufA + rowB*FP + col) = make_float2(oacc[c][2], oacc[c][3]);
        }
    }
    __syncthreads();
    if (wn == 0) {
        float lA = psum[rowA] + psum[64 + rowA] + psum[128 + rowA] + psum[192 + rowA];
        float lB = psum[rowB] + psum[64 + rowB] + psum[128 + rowB] + psum[192 + rowB];
        float invA = 1.f / lA, invB = 1.f / lB;
        float* ObA = O + ((size_t)(b*SEQ + i0 + rowA)) * EDIM + h*HD;
        float* ObB = O + ((size_t)(b*SEQ + i0 + rowB)) * EDIM + h*HD;
#pragma unroll
        for (int c = 0; c < 8; c++) {
            int col = (c << 3) + (tg << 1);
            float2 vA = *(float2*)(BufA + rowA*FP + col);
            float2 vB = *(float2*)(BufA + rowB*FP + col);
            *(float2*)(ObA + col) = make_float2((oacc[c][0] + vA.x) * invA,
                                                (oacc[c][1] + vA.y) * invA);
            *(float2*)(ObB + col) = make_float2((oacc[c][2] + vB.x) * invB,
                                                (oacc[c][3] + vB.y) * invB);
        }
    }
}

// ============================================================
extern "C" void kernel_launch(void* const* d_in, const int* in_sizes, int n_in,
                              void* d_out, int out_size)
{
    const float* query = (const float*)d_in[0];
    const float* key_  = (const float*)d_in[1];
    const float* value = (const float*)d_in[2];
    const unsigned char* mask = (const unsigned char*)d_in[3];
    const float* Wq = (const float*)d_in[4];
    const float* bq = (const float*)d_in[5];
    const float* Wk = (const float*)d_in[6];
    const float* bk = (const float*)d_in[7];
    const float* Wv = (const float*)d_in[8];
    const float* bv = (const float*)d_in[9];
    const float* Wo = (const float*)d_in[10];
    const float* bo = (const float*)d_in[11];
    const float* rel_emb = (const float*)d_in[12];
    const float* Wp = (const float*)d_in[13];
    float* out = (float*)d_out;

    float *Qg, *Kg, *Vg, *Cg, *Rkg;
    cudaGetSymbolAddress((void**)&Qg,  g_Q);
    cudaGetSymbolAddress((void**)&Kg,  g_K);
    cudaGetSymbolAddress((void**)&Vg,  g_V);
    cudaGetSymbolAddress((void**)&Cg,  g_ctx);
    cudaGetSymbolAddress((void**)&Rkg, g_Rk);

    cudaFuncSetAttribute(gemm_qkv,
                         cudaFuncAttributeMaxDynamicSharedMemorySize, GEMM_SMEM);
    cudaFuncSetAttribute(gemm_out,
                         cudaFuncAttributeMaxDynamicSharedMemorySize, GEMM_SMEM);
    cudaFuncSetAttribute(flash_rel_mma,
                         cudaFuncAttributeMaxDynamicSharedMemorySize, FLASH_SMEM);

    dim3 gblk(256);

    dim3 gq(EDIM/128, MTOT/128, 3);
    gemm_qkv<<<gq, gblk, GEMM_SMEM>>>(query, key_, value, Wq, Wk, Wv,
                                      bq, bk, bv, Qg, Kg, Vg);
    relproj2_kernel<<<(NREL + 31)/32, 256>>>(rel_emb, Wp, Rkg);

    dim3 fgrid(SEQ/64, NH, BATCH);
    flash_rel_mma<<<fgrid, 512, FLASH_SMEM>>>(Qg, Kg, Vg, mask, Rkg, Cg);

    dim3 go(EDIM/128, MTOT/128, 1);
    gemm_out<<<go, gblk, GEMM_SMEM>>>(Cg, Wo, bo, out);
}